// round 1
// baseline (speedup 1.0000x reference)
#include <cuda_runtime.h>
#include <cuda_bf16.h>

#define NX 192
#define NY 192
#define NZ 192
#define BX 32
#define BY 8
#define NTHREADS (BX * BY)
#define ZCHUNK 48
#define TILE_W (BX + 2)          // 34
#define TILE_H (BY + 2)          // 10
#define TILE_N (TILE_W * TILE_H) // 340

__device__ double g_acc = 0.0;

__device__ __forceinline__ void load_plane(const float* __restrict__ src,
                                           float* __restrict__ tile,
                                           int gz, int x0, int y0, int tid) {
    const float* plane = src + (size_t)gz * (NX * NY);
#pragma unroll
    for (int i = tid; i < TILE_N; i += NTHREADS) {
        int ly = i / TILE_W;
        int lx = i - ly * TILE_W;
        int gy = y0 + ly - 1;
        gy = gy < 0 ? 0 : (gy > NY - 1 ? NY - 1 : gy);
        int gx = x0 + lx - 1;
        gx = gx < 0 ? 0 : (gx > NX - 1 ? NX - 1 : gx);
        tile[i] = plane[gy * NX + gx];
    }
}

// Per-plane 2D stats from the 3x3 neighborhood in shared memory:
//   gx = colsum(x+1) - colsum(x-1)   (-> Ix after z-sum)
//   gy = rowsum(y+1) - rowsum(y-1)   (-> Iy after z-sum)
//   b  = full 3x3 box sum            (-> Iz via b(z+1)-b(z-1))
__device__ __forceinline__ void plane_stats(const float* __restrict__ tile,
                                            int tx, int ty,
                                            float& gx, float& gy, float& b) {
    const float* r0 = tile + ty * TILE_W + tx;  // row (y-1) in tile coords
    const float* r1 = r0 + TILE_W;
    const float* r2 = r1 + TILE_W;
    float a00 = r0[0], a01 = r0[1], a02 = r0[2];
    float a10 = r1[0], a11 = r1[1], a12 = r1[2];
    float a20 = r2[0], a21 = r2[1], a22 = r2[2];
    float c0 = a00 + a10 + a20;
    float c1 = a01 + a11 + a21;
    float c2 = a02 + a12 + a22;
    b  = c0 + c1 + c2;
    gx = c2 - c0;
    gy = (a20 + a21 + a22) - (a00 + a01 + a02);
}

__global__ __launch_bounds__(NTHREADS)
void ngf_kernel(const float* __restrict__ I,
                const float* __restrict__ J,
                const float* __restrict__ M) {
    __shared__ float sI[TILE_N];
    __shared__ float sJ[TILE_N];
    __shared__ float warp_sums[NTHREADS / 32];

    const int tx  = threadIdx.x;
    const int ty  = threadIdx.y;
    const int tid = ty * BX + tx;
    const int x0  = blockIdx.x * BX;
    const int y0  = blockIdx.y * BY;
    const int z0  = blockIdx.z * ZCHUNK;
    const int x   = x0 + tx;
    const int y   = y0 + ty;

    // Rolling per-plane stats: [0] = z-1, [1] = z, [2] = z+1 (relative to output z)
    float gxI0 = 0, gxI1 = 0, gyI0 = 0, gyI1 = 0, bI0 = 0, bI1 = 0;
    float gxJ0 = 0, gxJ1 = 0, gyJ0 = 0, gyJ1 = 0, bJ0 = 0, bJ1 = 0;

    float acc = 0.0f;

    const float* mrow = M + (size_t)y * NX + x;

    for (int zp = z0 - 1; zp <= z0 + ZCHUNK; ++zp) {
        int gz = zp < 0 ? 0 : (zp > NZ - 1 ? NZ - 1 : zp);
        __syncthreads();
        load_plane(I, sI, gz, x0, y0, tid);
        load_plane(J, sJ, gz, x0, y0, tid);
        __syncthreads();

        float gxi, gyi, bi, gxj, gyj, bj;
        plane_stats(sI, tx, ty, gxi, gyi, bi);
        plane_stats(sJ, tx, ty, gxj, gyj, bj);

        if (zp >= z0 + 1) {
            const int z = zp - 1;
            // Unscaled gradient sums (true gradient = 0.5 * these)
            float Ix = gxI0 + gxI1 + gxi;
            float Iy = gyI0 + gyI1 + gyi;
            float Iz = bi - bI0;
            float Jx = gxJ0 + gxJ1 + gxj;
            float Jy = gyJ0 + gyJ1 + gyj;
            float Jz = bj - bJ0;

            // I_mag_true = 0.25*ssi + EPS^2 (EPS=0.1), dot_true = 0.25*sdot
            float ssi  = fmaf(Ix, Ix, fmaf(Iy, Iy, Iz * Iz));
            float ssj  = fmaf(Jx, Jx, fmaf(Jy, Jy, Jz * Jz));
            float sdot = fmaf(Ix, Jx, fmaf(Iy, Jy, Iz * Jz));

            float imag = fmaf(0.25f, ssi, 0.01f);
            float jmag = fmaf(0.25f, ssj, 0.01f);
            float ngf  = (0.0625f * sdot * sdot) * __frcp_rn(imag * jmag);

            float m = mrow[(size_t)z * (NX * NY)];
            acc += (1.0f - ngf) * m;
        }

        // shift rolling state
        gxI0 = gxI1; gxI1 = gxi;
        gyI0 = gyI1; gyI1 = gyi;
        bI0  = bI1;  bI1  = bi;
        gxJ0 = gxJ1; gxJ1 = gxj;
        gyJ0 = gyJ1; gyJ1 = gyj;
        bJ0  = bJ1;  bJ1  = bj;
    }

    // Block reduction
#pragma unroll
    for (int off = 16; off > 0; off >>= 1)
        acc += __shfl_xor_sync(0xFFFFFFFFu, acc, off);
    if ((tid & 31) == 0) warp_sums[tid >> 5] = acc;
    __syncthreads();
    if (tid < 32) {
        float v = (tid < NTHREADS / 32) ? warp_sums[tid] : 0.0f;
#pragma unroll
        for (int off = 4; off > 0; off >>= 1)
            v += __shfl_xor_sync(0xFFFFFFFFu, v, off);
        if (tid == 0) atomicAdd(&g_acc, (double)v);
    }
}

__global__ void ngf_finalize(float* __restrict__ out) {
    const double inv_n = 1.0 / (double)((long long)NX * NY * NZ);
    out[0] = (float)(g_acc * inv_n);
    g_acc = 0.0;  // reset for the next graph replay (deterministic)
}

extern "C" void kernel_launch(void* const* d_in, const int* in_sizes, int n_in,
                              void* d_out, int out_size) {
    const float* I = (const float*)d_in[0];
    const float* J = (const float*)d_in[1];
    const float* M = (const float*)d_in[2];
    float* out = (float*)d_out;

    dim3 block(BX, BY, 1);
    dim3 grid(NX / BX, NY / BY, NZ / ZCHUNK);  // 6 x 24 x 4 = 576 CTAs
    ngf_kernel<<<grid, block>>>(I, J, M);
    ngf_finalize<<<1, 1>>>(out);
}

// round 2
// speedup vs baseline: 1.2290x; 1.2290x over previous
#include <cuda_runtime.h>
#include <cuda_bf16.h>

#define NX 192
#define NY 192
#define NZ 192
#define NXY (NX * NY)

#define BXD 32                 // lanes = x
#define WYD 4                  // warps per block, each owns YPT y-rows
#define YPT 4
#define ZCHUNK 24
#define NTHREADS (BXD * WYD)   // 128
#define GXB (NX / BXD)         // 6
#define GYB (NY / (WYD * YPT)) // 12
#define GZB (NZ / ZCHUNK)      // 8
#define NBLOCKS (GXB * GYB * GZB) // 576

__device__ double g_acc = 0.0;
__device__ unsigned int g_done = 0;

// Per-plane 2D stats for YPT output rows, x via shuffles, y via registers:
//   gxp = sum_{dy} [v(x+1)-v(x-1)]   (-> Ix after z triple-sum)
//   gyp = rowsum(y+1) - rowsum(y-1)  (-> Iy after z triple-sum)
//   bp  = 3x3 box sum                (-> Iz via b(z+1)-b(z-1))
__device__ __forceinline__ void plane_pass(
    const float* __restrict__ plane, const int* __restrict__ rowoff,
    int x, int xe, bool edge, int lane,
    float* __restrict__ gxp, float* __restrict__ gyp, float* __restrict__ bp)
{
    float h[YPT + 2], d[YPT + 2];
#pragma unroll
    for (int r = 0; r < YPT + 2; ++r) {
        const float* row = plane + rowoff[r];
        float v  = row[x];
        float vm = __shfl_up_sync(0xFFFFFFFFu, v, 1);
        float vp = __shfl_down_sync(0xFFFFFFFFu, v, 1);
        float ve = 0.0f;
        if (edge) ve = row[xe];           // one predicated LDG, lanes 0 & 31 only
        if (lane == 0)  vm = ve;
        if (lane == 31) vp = ve;
        h[r] = vm + v + vp;
        d[r] = vp - vm;
    }
#pragma unroll
    for (int i = 0; i < YPT; ++i) {
        gxp[i] = d[i] + d[i + 1] + d[i + 2];
        gyp[i] = h[i + 2] - h[i];
        bp[i]  = h[i] + h[i + 1] + h[i + 2];
    }
}

__global__ __launch_bounds__(NTHREADS)
void ngf_kernel(const float* __restrict__ I,
                const float* __restrict__ J,
                const float* __restrict__ M,
                float* __restrict__ out)
{
    __shared__ float warp_sums[WYD];

    const int lane = threadIdx.x;
    const int wy   = threadIdx.y;
    const int tid  = wy * BXD + lane;
    const int x    = blockIdx.x * BXD + lane;
    const int yb   = blockIdx.y * (WYD * YPT) + wy * YPT;
    const int z0   = blockIdx.z * ZCHUNK;

    // Clamped row offsets (y dimension), constant across z
    int rowoff[YPT + 2];
#pragma unroll
    for (int r = 0; r < YPT + 2; ++r) {
        int gy = yb - 1 + r;
        gy = gy < 0 ? 0 : (gy > NY - 1 ? NY - 1 : gy);
        rowoff[r] = gy * NX;
    }

    const bool edge = (lane == 0) || (lane == 31);
    int xe;
    {
        int xm = x - 1 < 0 ? 0 : x - 1;
        int xp = x + 1 > NX - 1 ? NX - 1 : x + 1;
        xe = (lane == 0) ? xm : xp;
    }

    // Rolling z state: [0] = plane z-1, [1] = plane z (relative to next output)
    float gxI0[YPT], gxI1[YPT], gyI0[YPT], gyI1[YPT], bI0[YPT], bI1[YPT];
    float gxJ0[YPT], gxJ1[YPT], gyJ0[YPT], gyJ1[YPT], bJ0[YPT], bJ1[YPT];
#pragma unroll
    for (int i = 0; i < YPT; ++i) {
        gxI0[i] = gxI1[i] = gyI0[i] = gyI1[i] = bI0[i] = bI1[i] = 0.0f;
        gxJ0[i] = gxJ1[i] = gyJ0[i] = gyJ1[i] = bJ0[i] = bJ1[i] = 0.0f;
    }

    float acc = 0.0f;

    for (int zp = z0 - 1; zp <= z0 + ZCHUNK; ++zp) {
        int gz = zp < 0 ? 0 : (zp > NZ - 1 ? NZ - 1 : zp);
        const float* pI = I + (size_t)gz * NXY;
        const float* pJ = J + (size_t)gz * NXY;

        float gxi[YPT], gyi[YPT], bi[YPT];
        float gxj[YPT], gyj[YPT], bj[YPT];
        plane_pass(pI, rowoff, x, xe, edge, lane, gxi, gyi, bi);
        plane_pass(pJ, rowoff, x, xe, edge, lane, gxj, gyj, bj);

        if (zp >= z0 + 1) {
            const int z = zp - 1;
            const float* mplane = M + (size_t)z * NXY;
#pragma unroll
            for (int i = 0; i < YPT; ++i) {
                // Unscaled gradient sums (true gradient = 0.5 * these)
                float Ix = gxI0[i] + gxI1[i] + gxi[i];
                float Iy = gyI0[i] + gyI1[i] + gyi[i];
                float Iz = bi[i] - bI0[i];
                float Jx = gxJ0[i] + gxJ1[i] + gxj[i];
                float Jy = gyJ0[i] + gyJ1[i] + gyj[i];
                float Jz = bj[i] - bJ0[i];

                float ssi  = fmaf(Ix, Ix, fmaf(Iy, Iy, Iz * Iz));
                float ssj  = fmaf(Jx, Jx, fmaf(Jy, Jy, Jz * Jz));
                float sdot = fmaf(Ix, Jx, fmaf(Iy, Jy, Iz * Jz));

                float imag = fmaf(0.25f, ssi, 0.01f);   // 0.25*ssi + EPS^2
                float jmag = fmaf(0.25f, ssj, 0.01f);
                float ngf  = __fdividef(0.0625f * sdot * sdot, imag * jmag);

                float m = mplane[rowoff[i + 1] + x];    // rowoff[i+1] == (yb+i)*NX
                acc = fmaf(1.0f - ngf, m, acc);
            }
        }

        // Shift rolling state
#pragma unroll
        for (int i = 0; i < YPT; ++i) {
            gxI0[i] = gxI1[i]; gxI1[i] = gxi[i];
            gyI0[i] = gyI1[i]; gyI1[i] = gyi[i];
            bI0[i]  = bI1[i];  bI1[i]  = bi[i];
            gxJ0[i] = gxJ1[i]; gxJ1[i] = gxj[i];
            gyJ0[i] = gyJ1[i]; gyJ1[i] = gyj[i];
            bJ0[i]  = bJ1[i];  bJ1[i]  = bj[i];
        }
    }

    // Block reduction
#pragma unroll
    for (int off = 16; off > 0; off >>= 1)
        acc += __shfl_xor_sync(0xFFFFFFFFu, acc, off);
    if (lane == 0) warp_sums[wy] = acc;
    __syncthreads();

    if (tid == 0) {
        float v = warp_sums[0] + warp_sums[1] + warp_sums[2] + warp_sums[3];
        atomicAdd(&g_acc, (double)v);
        __threadfence();
        unsigned prev = atomicAdd(&g_done, 1u);
        if (prev == NBLOCKS - 1) {
            // Last block: all other blocks' g_acc adds are fenced before their
            // g_done increments, so an atomic read here sees the full sum.
            double tot = atomicAdd(&g_acc, 0.0);
            out[0] = (float)(tot * (1.0 / (double)((long long)NX * NY * NZ)));
            g_acc = 0.0;       // reset for next replay (deterministic)
            __threadfence();
            g_done = 0;
        }
    }
}

extern "C" void kernel_launch(void* const* d_in, const int* in_sizes, int n_in,
                              void* d_out, int out_size) {
    const float* I = (const float*)d_in[0];
    const float* J = (const float*)d_in[1];
    const float* M = (const float*)d_in[2];
    float* out = (float*)d_out;

    dim3 block(BXD, WYD, 1);
    dim3 grid(GXB, GYB, GZB);   // 6 x 12 x 8 = 576 CTAs
    ngf_kernel<<<grid, block>>>(I, J, M, out);
}